// round 2
// baseline (speedup 1.0000x reference)
#include <cuda_runtime.h>
#include <cuda_bf16.h>

#define HH 256
#define WW 256
#define BATCH 16

// ---------------- scratch (device globals; no allocations allowed) ----------
__device__ float  g_y1[(size_t)BATCH * 32 * HH * WW];   // conv1 raw output (134 MB)
__device__ float  g_y2[(size_t)BATCH * 64 * HH * WW];   // conv2 raw output (268 MB)
__device__ double g_sum[3][128];
__device__ double g_sumsq[3][128];
__device__ float  g_scale[3][128];
__device__ float  g_shift[3][128];
__device__ float  g_zraw[2][BATCH][128];                // raw conv3 at anchor/positive
__device__ float  g_w1T[3 * 9 * 32];                    // weights transposed [ci][tap][co]
__device__ float  g_w2T[32 * 9 * 64];
__device__ float  g_w3T[64 * 9 * 128];

// ---------------- f32x2 helpers ---------------------------------------------
__device__ __forceinline__ void ffma2(unsigned long long& acc,
                                      unsigned long long a,
                                      unsigned long long w) {
    asm("fma.rn.f32x2 %0, %1, %2, %0;" : "+l"(acc) : "l"(a), "l"(w));
}
__device__ __forceinline__ unsigned long long pack2(float w) {
    unsigned long long r;
    asm("mov.b64 %0, {%1, %1};" : "=l"(r) : "f"(w));
    return r;
}
__device__ __forceinline__ float lo2(unsigned long long u) {
    return __uint_as_float((unsigned)u);
}
__device__ __forceinline__ float hi2(unsigned long long u) {
    return __uint_as_float((unsigned)(u >> 32));
}

// ---------------- small helper kernels --------------------------------------
__global__ void zero_stats_kernel() {
    int i = threadIdx.x;
    if (i < 384) {
        ((double*)g_sum)[i]   = 0.0;
        ((double*)g_sumsq)[i] = 0.0;
    }
}

__global__ void transpose_weights_kernel(const float* __restrict__ w1,
                                         const float* __restrict__ w2,
                                         const float* __restrict__ w3) {
    int idx = blockIdx.x * 256 + threadIdx.x;
    if (idx < 32 * 3 * 9) {   // conv1: OIHW (32,3,3,3)
        int co = idx / 27, r = idx % 27, ci = r / 9, t = r % 9;
        g_w1T[(ci * 9 + t) * 32 + co] = w1[idx];
    }
    if (idx < 64 * 32 * 9) {  // conv2: (64,32,3,3)
        int co = idx / 288, r = idx % 288, ci = r / 9, t = r % 9;
        g_w2T[(ci * 9 + t) * 64 + co] = w2[idx];
    }
    if (idx < 128 * 64 * 9) { // conv3: (128,64,3,3)
        int co = idx / 576, r = idx % 576, ci = r / 9, t = r % 9;
        g_w3T[(ci * 9 + t) * 128 + co] = w3[idx];
    }
}

__global__ void bnparams_kernel(int layer, int C,
                                const float* __restrict__ gamma,
                                const float* __restrict__ beta) {
    int c = threadIdx.x;
    if (c < C) {
        const double n = (double)BATCH * HH * WW;
        double mean = g_sum[layer][c] / n;
        double var  = g_sumsq[layer][c] / n - mean * mean;
        float sc = gamma[c] * (float)(1.0 / sqrt(var + 1e-5));
        g_scale[layer][c] = sc;
        g_shift[layer][c] = beta[c] - (float)mean * sc;
    }
}

// ---------------- fused conv + stats kernel (f32x2) --------------------------
// Block: 128 threads = 4 warps. Tile: 8 output rows x 32 cols.
// Each warp owns 2 output rows (2*warp, 2*warp+1); lane <-> cout within a
// 32-channel group. Inputs staged as duplicated pairs s_in[..][c] = {v[c],v[c+1]}
// so a single broadcast LDS.128 at entry 2k yields both the even pair E_k and
// the odd pair O_k; all three 3x1 taps come from {E_k, O_k, E_{k+1}}.
template <int CIN, int CK, int GROUPS, int LAYER_IN, int LAYER_OUT,
          bool WRITE_OUT, bool QUERY>
__global__ __launch_bounds__(128)
void conv_kernel(const float* __restrict__ in, const float* __restrict__ wT,
                 const float* __restrict__ bias, float* __restrict__ out,
                 const int* __restrict__ anchors, const int* __restrict__ positives) {
    constexpr int COUT = GROUPS * 32;
    __shared__ alignas(16) float2 s_in[CK][10][34]; // pair-duplicated input tile
    __shared__ float s_w[CK][9][32];                // weights for this cout group
    __shared__ float s_out[4][32][33];              // half-tile transpose (+pad)
    __shared__ float s_red[2][4][32];               // stats block-reduce

    const int tid  = threadIdx.x;
    const int lane = tid & 31;
    const int warp = tid >> 5;
    const int b    = blockIdx.z / GROUPS;
    const int g    = blockIdx.z % GROUPS;
    const int gy0  = blockIdx.y * 8;
    const int gx0  = blockIdx.x * 32;
    const int cout = g * 32 + lane;
    const int row0 = 2 * warp;          // tile-local first output row

    unsigned long long accA[16], accB[16];   // rows row0, row0+1; pair k = x(2k,2k+1)
#pragma unroll
    for (int k = 0; k < 16; ++k) { accA[k] = 0ull; accB[k] = 0ull; }

    for (int cc = 0; cc < CIN; cc += CK) {
        __syncthreads();  // prior chunk's readers done before restage
        // ---- stage input pairs (BN + LReLU of previous layer applied) ------
        for (int idx = tid; idx < CK * 10 * 33; idx += 128) {
            int ci = idx / 330; int rem = idx - ci * 330;
            int r = rem / 33;   int c = rem - r * 33;
            int iy = gy0 - 1 + r;
            float v0 = 0.f, v1 = 0.f;
            if ((unsigned)iy < 256u) {
                int ch = cc + ci;
                const float* base = in + (((size_t)b * CIN + ch) * HH + iy) * WW;
                float sc = 1.f, sh = 0.f;
                if constexpr (LAYER_IN >= 0) {
                    constexpr int LI = (LAYER_IN >= 0) ? LAYER_IN : 0;
                    sc = g_scale[LI][ch]; sh = g_shift[LI][ch];
                }
                int ix0 = gx0 - 1 + c;
                if ((unsigned)ix0 < 256u) {
                    v0 = base[ix0];
                    if constexpr (LAYER_IN >= 0) {
                        float t = fmaf(v0, sc, sh);
                        v0 = (t >= 0.f) ? t : 0.01f * t;
                    }
                }
                int ix1 = ix0 + 1;
                if ((unsigned)ix1 < 256u) {
                    v1 = base[ix1];
                    if constexpr (LAYER_IN >= 0) {
                        float t = fmaf(v1, sc, sh);
                        v1 = (t >= 0.f) ? t : 0.01f * t;
                    }
                }
            }
            s_in[ci][r][c] = make_float2(v0, v1);
        }
        // ---- stage weights (coalesced: cout contiguous in wT) --------------
        for (int idx = tid; idx < CK * 9 * 32; idx += 128) {
            int ci = idx / 288; int rem = idx - ci * 288;
            int t = rem >> 5;   int co = rem & 31;
            s_w[ci][t][co] = wT[((size_t)(cc + ci) * 9 + t) * COUT + g * 32 + co];
        }
        __syncthreads();
        // ---- compute -------------------------------------------------------
        for (int ci = 0; ci < CK; ++ci) {
            unsigned long long wp[9];
#pragma unroll
            for (int t = 0; t < 9; ++t) wp[t] = pack2(s_w[ci][t][lane]);
#pragma unroll
            for (int ri = 0; ri < 4; ++ri) {
                // input row (tile-local, s_in row index) = row0 + ri
                const unsigned long long* rp =
                    (const unsigned long long*)&s_in[ci][row0 + ri][0];
                const ulonglong2* rp2 = (const ulonglong2*)rp;
                ulonglong2 q = rp2[0];           // {E_0, O_0}
#pragma unroll
                for (int k = 0; k < 16; ++k) {
                    unsigned long long Ek = q.x, Ok = q.y, En;
                    if (k < 15) { q = rp2[k + 1]; En = q.x; }
                    else        { En = rp[32]; }
                    if (ri <= 2) {               // contributes to row0, dy = ri
                        ffma2(accA[k], Ek, wp[3 * ri + 0]);
                        ffma2(accA[k], Ok, wp[3 * ri + 1]);
                        ffma2(accA[k], En, wp[3 * ri + 2]);
                    }
                    if (ri >= 1) {               // contributes to row0+1, dy = ri-1
                        ffma2(accB[k], Ek, wp[3 * (ri - 1) + 0]);
                        ffma2(accB[k], Ok, wp[3 * (ri - 1) + 1]);
                        ffma2(accB[k], En, wp[3 * (ri - 1) + 2]);
                    }
                }
            }
        }
    }

    // ---- epilogue: bias + stats (block-reduced) -----------------------------
    const float bv = bias[cout];
    float lsum = 0.f, lsq = 0.f;
#pragma unroll
    for (int k = 0; k < 16; ++k) {
        float a0 = lo2(accA[k]) + bv, a1 = hi2(accA[k]) + bv;
        float b0 = lo2(accB[k]) + bv, b1 = hi2(accB[k]) + bv;
        lsum += (a0 + a1) + (b0 + b1);
        lsq = fmaf(a0, a0, lsq); lsq = fmaf(a1, a1, lsq);
        lsq = fmaf(b0, b0, lsq); lsq = fmaf(b1, b1, lsq);
    }
    s_red[0][warp][lane] = lsum;
    s_red[1][warp][lane] = lsq;
    __syncthreads();
    if (warp == 0) {
        float ts = (s_red[0][0][lane] + s_red[0][1][lane]) +
                   (s_red[0][2][lane] + s_red[0][3][lane]);
        float tq = (s_red[1][0][lane] + s_red[1][1][lane]) +
                   (s_red[1][2][lane] + s_red[1][3][lane]);
        atomicAdd(&g_sum[LAYER_OUT][cout],   (double)ts);
        atomicAdd(&g_sumsq[LAYER_OUT][cout], (double)tq);
    }

    // ---- output / query via two 4-row transpose passes ----------------------
#pragma unroll
    for (int h = 0; h < 2; ++h) {
        __syncthreads();
        if ((warp >> 1) == h) {
            int sr = row0 - 4 * h;               // 0 or 2
#pragma unroll
            for (int k = 0; k < 16; ++k) {
                s_out[sr    ][2 * k    ][lane] = lo2(accA[k]) + bv;
                s_out[sr    ][2 * k + 1][lane] = hi2(accA[k]) + bv;
                s_out[sr + 1][2 * k    ][lane] = lo2(accB[k]) + bv;
                s_out[sr + 1][2 * k + 1][lane] = hi2(accB[k]) + bv;
            }
        }
        __syncthreads();
        if constexpr (WRITE_OUT) {
            for (int combo = warp; combo < 128; combo += 4) {
                int r = combo >> 5, co = combo & 31;
                out[(((size_t)b * COUT + g * 32 + co) * HH + gy0 + 4 * h + r) * WW +
                    gx0 + lane] = s_out[r][lane][co];
            }
        }
        if constexpr (QUERY) {
            if (warp == 0) {
                int ah_ = anchors[b * 8 + 6], aw_ = anchors[b * 8 + 7];
                int lr = ah_ - (gy0 + 4 * h);
                if (lr >= 0 && lr < 4 && aw_ >= gx0 && aw_ < gx0 + 32)
                    g_zraw[0][b][cout] = s_out[lr][aw_ - gx0][lane];
                int ph_ = positives[b * 8 + 6], pw_ = positives[b * 8 + 7];
                int lp = ph_ - (gy0 + 4 * h);
                if (lp >= 0 && lp < 4 && pw_ >= gx0 && pw_ < gx0 + 32)
                    g_zraw[1][b][cout] = s_out[lp][pw_ - gx0][lane];
            }
        }
    }
}

// ---------------- final: BN3 + outputs + tiny recon GEMM + patch gather -----
__global__ void final_kernel(const float* __restrict__ x,
                             const int* __restrict__ anchors,
                             const int* __restrict__ positives,
                             const float* __restrict__ recon_w,
                             const float* __restrict__ recon_b,
                             float* __restrict__ out) {
    const int b = blockIdx.x, tid = threadIdx.x;
    __shared__ float za[128];
    if (tid < 128) {
        float s = g_scale[2][tid], sh = g_shift[2][tid];
        float v = fmaf(g_zraw[0][b][tid], s, sh);
        v = (v >= 0.f) ? v : 0.01f * v;
        za[tid] = v;
        out[4704 + b * 128 + tid] = v;          // z_anchors
        float vp = fmaf(g_zraw[1][b][tid], s, sh);
        vp = (vp >= 0.f) ? vp : 0.01f * vp;
        out[6752 + b * 128 + tid] = vp;         // z_positives
    }
    __syncthreads();
    if (tid < 147) {
        int ah = anchors[b * 8 + 6], aw = anchors[b * 8 + 7];
        int c = tid / 49, rem = tid % 49, i = rem / 7, j = rem % 7;
        out[b * 147 + tid] =
            x[(((size_t)b * 3 + c) * HH + (ah - 3 + i)) * WW + (aw - 3 + j)];  // x_anchors
        float sum = recon_b[tid];
#pragma unroll 4
        for (int cc = 0; cc < 128; ++cc)
            sum = fmaf(za[cc], recon_w[tid * 128 + cc], sum);
        out[2352 + b * 147 + tid] = sum;        // x_recon
    }
}

// ---------------- launch -----------------------------------------------------
extern "C" void kernel_launch(void* const* d_in, const int* in_sizes, int n_in,
                              void* d_out, int out_size) {
    (void)in_sizes; (void)n_in; (void)out_size;
    const float* x        = (const float*)d_in[0];
    const int*   anchors  = (const int*)  d_in[1];
    const int*   positives= (const int*)  d_in[2];
    const float* conv1_w  = (const float*)d_in[3];
    const float* conv1_b  = (const float*)d_in[4];
    const float* bn1_g    = (const float*)d_in[5];
    const float* bn1_b    = (const float*)d_in[6];
    const float* conv2_w  = (const float*)d_in[7];
    const float* conv2_b  = (const float*)d_in[8];
    const float* bn2_g    = (const float*)d_in[9];
    const float* bn2_b    = (const float*)d_in[10];
    const float* conv3_w  = (const float*)d_in[11];
    const float* conv3_b  = (const float*)d_in[12];
    const float* bn3_g    = (const float*)d_in[13];
    const float* bn3_b    = (const float*)d_in[14];
    const float* recon_w  = (const float*)d_in[15];
    const float* recon_b  = (const float*)d_in[16];
    float* out = (float*)d_out;

    float *p_y1, *p_y2, *p_w1T, *p_w2T, *p_w3T;
    cudaGetSymbolAddress((void**)&p_y1,  g_y1);
    cudaGetSymbolAddress((void**)&p_y2,  g_y2);
    cudaGetSymbolAddress((void**)&p_w1T, g_w1T);
    cudaGetSymbolAddress((void**)&p_w2T, g_w2T);
    cudaGetSymbolAddress((void**)&p_w3T, g_w3T);

    zero_stats_kernel<<<1, 384>>>();
    transpose_weights_kernel<<<288, 256>>>(conv1_w, conv2_w, conv3_w);

    dim3 grid1(WW / 32, HH / 8, BATCH * 1);
    conv_kernel<3, 3, 1, -1, 0, true, false><<<grid1, 128>>>(
        x, p_w1T, conv1_b, p_y1, anchors, positives);
    bnparams_kernel<<<1, 128>>>(0, 32, bn1_g, bn1_b);

    dim3 grid2(WW / 32, HH / 8, BATCH * 2);
    conv_kernel<32, 8, 2, 0, 1, true, false><<<grid2, 128>>>(
        p_y1, p_w2T, conv2_b, p_y2, anchors, positives);
    bnparams_kernel<<<1, 128>>>(1, 64, bn2_g, bn2_b);

    dim3 grid3(WW / 32, HH / 8, BATCH * 4);
    conv_kernel<64, 8, 4, 1, 2, false, true><<<grid3, 128>>>(
        p_y2, p_w3T, conv3_b, nullptr, anchors, positives);
    bnparams_kernel<<<1, 128>>>(2, 128, bn3_g, bn3_b);

    final_kernel<<<BATCH, 256>>>(x, anchors, positives, recon_w, recon_b, out);
}

// round 6
// speedup vs baseline: 1.0002x; 1.0002x over previous
#include <cuda_runtime.h>
#include <cuda_bf16.h>

#define HH 256
#define WW 256
#define BATCH 16

// ---------------- scratch (device globals; no allocations allowed) ----------
__device__ float  g_y1[(size_t)BATCH * 32 * HH * WW];   // conv1 raw output (134 MB)
__device__ float  g_y2[(size_t)BATCH * 64 * HH * WW];   // conv2 raw output (268 MB)
__device__ double g_sum[3][128];
__device__ double g_sumsq[3][128];
__device__ float  g_scale[3][128];
__device__ float  g_shift[3][128];
__device__ float  g_zraw[2][BATCH][128];                // raw conv3 at anchor/positive
__device__ float  g_w1T[3 * 9 * 32];                    // weights transposed [ci][tap][co]
__device__ float  g_w2T[32 * 9 * 64];
__device__ float  g_w3T[64 * 9 * 128];

// ---------------- f32x2 helpers ---------------------------------------------
__device__ __forceinline__ void ffma2(unsigned long long& acc,
                                      unsigned long long a,
                                      unsigned long long w) {
    asm("fma.rn.f32x2 %0, %1, %2, %0;" : "+l"(acc) : "l"(a), "l"(w));
}
__device__ __forceinline__ unsigned long long pack2(float w) {
    unsigned long long r;
    asm("mov.b64 %0, {%1, %1};" : "=l"(r) : "f"(w));
    return r;
}
__device__ __forceinline__ float lo2(unsigned long long u) {
    return __uint_as_float((unsigned)u);
}
__device__ __forceinline__ float hi2(unsigned long long u) {
    return __uint_as_float((unsigned)(u >> 32));
}

// ---------------- small helper kernels --------------------------------------
__global__ void zero_stats_kernel() {
    int i = threadIdx.x;
    if (i < 384) {
        ((double*)g_sum)[i]   = 0.0;
        ((double*)g_sumsq)[i] = 0.0;
    }
}

__global__ void transpose_weights_kernel(const float* __restrict__ w1,
                                         const float* __restrict__ w2,
                                         const float* __restrict__ w3) {
    int idx = blockIdx.x * 256 + threadIdx.x;
    if (idx < 32 * 3 * 9) {   // conv1: OIHW (32,3,3,3)
        int co = idx / 27, r = idx % 27, ci = r / 9, t = r % 9;
        g_w1T[(ci * 9 + t) * 32 + co] = w1[idx];
    }
    if (idx < 64 * 32 * 9) {  // conv2: (64,32,3,3)
        int co = idx / 288, r = idx % 288, ci = r / 9, t = r % 9;
        g_w2T[(ci * 9 + t) * 64 + co] = w2[idx];
    }
    if (idx < 128 * 64 * 9) { // conv3: (128,64,3,3)
        int co = idx / 576, r = idx % 576, ci = r / 9, t = r % 9;
        g_w3T[(ci * 9 + t) * 128 + co] = w3[idx];
    }
}

__global__ void bnparams_kernel(int layer, int C,
                                const float* __restrict__ gamma,
                                const float* __restrict__ beta) {
    int c = threadIdx.x;
    if (c < C) {
        const double n = (double)BATCH * HH * WW;
        double mean = g_sum[layer][c] / n;
        double var  = g_sumsq[layer][c] / n - mean * mean;
        float sc = gamma[c] * (float)(1.0 / sqrt(var + 1e-5));
        g_scale[layer][c] = sc;
        g_shift[layer][c] = beta[c] - (float)mean * sc;
    }
}

// ---------------- fused conv + stats kernel (f32x2) --------------------------
// Block: 128 threads = 4 warps. Tile: 8 output rows x 32 cols.
// Each warp owns 2 output rows (2*warp, 2*warp+1); lane <-> cout within a
// 32-channel group. Inputs staged as duplicated pairs s_in[..][c] = {v[c],v[c+1]}
// so a single broadcast LDS.128 at entry 2k yields both the even pair E_k and
// the odd pair O_k; all three 3x1 taps come from {E_k, O_k, E_{k+1}}.
template <int CIN, int CK, int GROUPS, int LAYER_IN, int LAYER_OUT,
          bool WRITE_OUT, bool QUERY>
__global__ __launch_bounds__(128)
void conv_kernel(const float* __restrict__ in, const float* __restrict__ wT,
                 const float* __restrict__ bias, float* __restrict__ out,
                 const int* __restrict__ anchors, const int* __restrict__ positives) {
    constexpr int COUT = GROUPS * 32;
    __shared__ alignas(16) float2 s_in[CK][10][34]; // pair-duplicated input tile
    __shared__ float s_w[CK][9][32];                // weights for this cout group
    __shared__ float s_out[4][32][33];              // half-tile transpose (+pad)
    __shared__ float s_red[2][4][32];               // stats block-reduce

    const int tid  = threadIdx.x;
    const int lane = tid & 31;
    const int warp = tid >> 5;
    const int b    = blockIdx.z / GROUPS;
    const int g    = blockIdx.z % GROUPS;
    const int gy0  = blockIdx.y * 8;
    const int gx0  = blockIdx.x * 32;
    const int cout = g * 32 + lane;
    const int row0 = 2 * warp;          // tile-local first output row

    unsigned long long accA[16], accB[16];   // rows row0, row0+1; pair k = x(2k,2k+1)
#pragma unroll
    for (int k = 0; k < 16; ++k) { accA[k] = 0ull; accB[k] = 0ull; }

    for (int cc = 0; cc < CIN; cc += CK) {
        __syncthreads();  // prior chunk's readers done before restage
        // ---- stage input pairs (BN + LReLU of previous layer applied) ------
        for (int idx = tid; idx < CK * 10 * 33; idx += 128) {
            int ci = idx / 330; int rem = idx - ci * 330;
            int r = rem / 33;   int c = rem - r * 33;
            int iy = gy0 - 1 + r;
            float v0 = 0.f, v1 = 0.f;
            if ((unsigned)iy < 256u) {
                int ch = cc + ci;
                const float* base = in + (((size_t)b * CIN + ch) * HH + iy) * WW;
                float sc = 1.f, sh = 0.f;
                if constexpr (LAYER_IN >= 0) {
                    constexpr int LI = (LAYER_IN >= 0) ? LAYER_IN : 0;
                    sc = g_scale[LI][ch]; sh = g_shift[LI][ch];
                }
                int ix0 = gx0 - 1 + c;
                if ((unsigned)ix0 < 256u) {
                    v0 = base[ix0];
                    if constexpr (LAYER_IN >= 0) {
                        float t = fmaf(v0, sc, sh);
                        v0 = (t >= 0.f) ? t : 0.01f * t;
                    }
                }
                int ix1 = ix0 + 1;
                if ((unsigned)ix1 < 256u) {
                    v1 = base[ix1];
                    if constexpr (LAYER_IN >= 0) {
                        float t = fmaf(v1, sc, sh);
                        v1 = (t >= 0.f) ? t : 0.01f * t;
                    }
                }
            }
            s_in[ci][r][c] = make_float2(v0, v1);
        }
        // ---- stage weights (coalesced: cout contiguous in wT) --------------
        for (int idx = tid; idx < CK * 9 * 32; idx += 128) {
            int ci = idx / 288; int rem = idx - ci * 288;
            int t = rem >> 5;   int co = rem & 31;
            s_w[ci][t][co] = wT[((size_t)(cc + ci) * 9 + t) * COUT + g * 32 + co];
        }
        __syncthreads();
        // ---- compute -------------------------------------------------------
        for (int ci = 0; ci < CK; ++ci) {
            unsigned long long wp[9];
#pragma unroll
            for (int t = 0; t < 9; ++t) wp[t] = pack2(s_w[ci][t][lane]);
#pragma unroll
            for (int ri = 0; ri < 4; ++ri) {
                // input row (tile-local, s_in row index) = row0 + ri
                const unsigned long long* rp =
                    (const unsigned long long*)&s_in[ci][row0 + ri][0];
                const ulonglong2* rp2 = (const ulonglong2*)rp;
                ulonglong2 q = rp2[0];           // {E_0, O_0}
#pragma unroll
                for (int k = 0; k < 16; ++k) {
                    unsigned long long Ek = q.x, Ok = q.y, En;
                    if (k < 15) { q = rp2[k + 1]; En = q.x; }
                    else        { En = rp[32]; }
                    if (ri <= 2) {               // contributes to row0, dy = ri
                        ffma2(accA[k], Ek, wp[3 * ri + 0]);
                        ffma2(accA[k], Ok, wp[3 * ri + 1]);
                        ffma2(accA[k], En, wp[3 * ri + 2]);
                    }
                    if (ri >= 1) {               // contributes to row0+1, dy = ri-1
                        ffma2(accB[k], Ek, wp[3 * (ri - 1) + 0]);
                        ffma2(accB[k], Ok, wp[3 * (ri - 1) + 1]);
                        ffma2(accB[k], En, wp[3 * (ri - 1) + 2]);
                    }
                }
            }
        }
    }

    // ---- epilogue: bias + stats (block-reduced) -----------------------------
    const float bv = bias[cout];
    float lsum = 0.f, lsq = 0.f;
#pragma unroll
    for (int k = 0; k < 16; ++k) {
        float a0 = lo2(accA[k]) + bv, a1 = hi2(accA[k]) + bv;
        float b0 = lo2(accB[k]) + bv, b1 = hi2(accB[k]) + bv;
        lsum += (a0 + a1) + (b0 + b1);
        lsq = fmaf(a0, a0, lsq); lsq = fmaf(a1, a1, lsq);
        lsq = fmaf(b0, b0, lsq); lsq = fmaf(b1, b1, lsq);
    }
    s_red[0][warp][lane] = lsum;
    s_red[1][warp][lane] = lsq;
    __syncthreads();
    if (warp == 0) {
        float ts = (s_red[0][0][lane] + s_red[0][1][lane]) +
                   (s_red[0][2][lane] + s_red[0][3][lane]);
        float tq = (s_red[1][0][lane] + s_red[1][1][lane]) +
                   (s_red[1][2][lane] + s_red[1][3][lane]);
        atomicAdd(&g_sum[LAYER_OUT][cout],   (double)ts);
        atomicAdd(&g_sumsq[LAYER_OUT][cout], (double)tq);
    }

    // ---- output / query via two 4-row transpose passes ----------------------
#pragma unroll
    for (int h = 0; h < 2; ++h) {
        __syncthreads();
        if ((warp >> 1) == h) {
            int sr = row0 - 4 * h;               // 0 or 2
#pragma unroll
            for (int k = 0; k < 16; ++k) {
                s_out[sr    ][2 * k    ][lane] = lo2(accA[k]) + bv;
                s_out[sr    ][2 * k + 1][lane] = hi2(accA[k]) + bv;
                s_out[sr + 1][2 * k    ][lane] = lo2(accB[k]) + bv;
                s_out[sr + 1][2 * k + 1][lane] = hi2(accB[k]) + bv;
            }
        }
        __syncthreads();
        if constexpr (WRITE_OUT) {
            for (int combo = warp; combo < 128; combo += 4) {
                int r = combo >> 5, co = combo & 31;
                out[(((size_t)b * COUT + g * 32 + co) * HH + gy0 + 4 * h + r) * WW +
                    gx0 + lane] = s_out[r][lane][co];
            }
        }
        if constexpr (QUERY) {
            if (warp == 0) {
                int ah_ = anchors[b * 8 + 6], aw_ = anchors[b * 8 + 7];
                int lr = ah_ - (gy0 + 4 * h);
                if (lr >= 0 && lr < 4 && aw_ >= gx0 && aw_ < gx0 + 32)
                    g_zraw[0][b][cout] = s_out[lr][aw_ - gx0][lane];
                int ph_ = positives[b * 8 + 6], pw_ = positives[b * 8 + 7];
                int lp = ph_ - (gy0 + 4 * h);
                if (lp >= 0 && lp < 4 && pw_ >= gx0 && pw_ < gx0 + 32)
                    g_zraw[1][b][cout] = s_out[lp][pw_ - gx0][lane];
            }
        }
    }
}

// ---------------- final: BN3 + outputs + tiny recon GEMM + patch gather -----
__global__ void final_kernel(const float* __restrict__ x,
                             const int* __restrict__ anchors,
                             const int* __restrict__ positives,
                             const float* __restrict__ recon_w,
                             const float* __restrict__ recon_b,
                             float* __restrict__ out) {
    const int b = blockIdx.x, tid = threadIdx.x;
    __shared__ float za[128];
    if (tid < 128) {
        float s = g_scale[2][tid], sh = g_shift[2][tid];
        float v = fmaf(g_zraw[0][b][tid], s, sh);
        v = (v >= 0.f) ? v : 0.01f * v;
        za[tid] = v;
        out[4704 + b * 128 + tid] = v;          // z_anchors
        float vp = fmaf(g_zraw[1][b][tid], s, sh);
        vp = (vp >= 0.f) ? vp : 0.01f * vp;
        out[6752 + b * 128 + tid] = vp;         // z_positives
    }
    __syncthreads();
    if (tid < 147) {
        int ah = anchors[b * 8 + 6], aw = anchors[b * 8 + 7];
        int c = tid / 49, rem = tid % 49, i = rem / 7, j = rem % 7;
        out[b * 147 + tid] =
            x[(((size_t)b * 3 + c) * HH + (ah - 3 + i)) * WW + (aw - 3 + j)];  // x_anchors
        float sum = recon_b[tid];
#pragma unroll 4
        for (int cc = 0; cc < 128; ++cc)
            sum = fmaf(za[cc], recon_w[tid * 128 + cc], sum);
        out[2352 + b * 147 + tid] = sum;        // x_recon
    }
}

// ---------------- launch -----------------------------------------------------
extern "C" void kernel_launch(void* const* d_in, const int* in_sizes, int n_in,
                              void* d_out, int out_size) {
    (void)in_sizes; (void)n_in; (void)out_size;
    const float* x        = (const float*)d_in[0];
    const int*   anchors  = (const int*)  d_in[1];
    const int*   positives= (const int*)  d_in[2];
    const float* conv1_w  = (const float*)d_in[3];
    const float* conv1_b  = (const float*)d_in[4];
    const float* bn1_g    = (const float*)d_in[5];
    const float* bn1_b    = (const float*)d_in[6];
    const float* conv2_w  = (const float*)d_in[7];
    const float* conv2_b  = (const float*)d_in[8];
    const float* bn2_g    = (const float*)d_in[9];
    const float* bn2_b    = (const float*)d_in[10];
    const float* conv3_w  = (const float*)d_in[11];
    const float* conv3_b  = (const float*)d_in[12];
    const float* bn3_g    = (const float*)d_in[13];
    const float* bn3_b    = (const float*)d_in[14];
    const float* recon_w  = (const float*)d_in[15];
    const float* recon_b  = (const float*)d_in[16];
    float* out = (float*)d_out;

    float *p_y1, *p_y2, *p_w1T, *p_w2T, *p_w3T;
    cudaGetSymbolAddress((void**)&p_y1,  g_y1);
    cudaGetSymbolAddress((void**)&p_y2,  g_y2);
    cudaGetSymbolAddress((void**)&p_w1T, g_w1T);
    cudaGetSymbolAddress((void**)&p_w2T, g_w2T);
    cudaGetSymbolAddress((void**)&p_w3T, g_w3T);

    zero_stats_kernel<<<1, 384>>>();
    transpose_weights_kernel<<<288, 256>>>(conv1_w, conv2_w, conv3_w);

    dim3 grid1(WW / 32, HH / 8, BATCH * 1);
    conv_kernel<3, 3, 1, -1, 0, true, false><<<grid1, 128>>>(
        x, p_w1T, conv1_b, p_y1, anchors, positives);
    bnparams_kernel<<<1, 128>>>(0, 32, bn1_g, bn1_b);

    dim3 grid2(WW / 32, HH / 8, BATCH * 2);
    conv_kernel<32, 8, 2, 0, 1, true, false><<<grid2, 128>>>(
        p_y1, p_w2T, conv2_b, p_y2, anchors, positives);
    bnparams_kernel<<<1, 128>>>(1, 64, bn2_g, bn2_b);

    dim3 grid3(WW / 32, HH / 8, BATCH * 4);
    conv_kernel<64, 8, 4, 1, 2, false, true><<<grid3, 128>>>(
        p_y2, p_w3T, conv3_b, nullptr, anchors, positives);
    bnparams_kernel<<<1, 128>>>(2, 128, bn3_g, bn3_b);

    final_kernel<<<BATCH, 256>>>(x, anchors, positives, recon_w, recon_b, out);
}

// round 14
// speedup vs baseline: 1.3150x; 1.3148x over previous
#include <cuda_runtime.h>
#include <cuda_bf16.h>
#include <cstdint>

#define HH 256
#define WW 256
#define BATCH 16

// ---------------- scratch ----------------------------------------------------
__device__ float  g_y1[(size_t)BATCH * 32 * HH * WW];
__device__ float  g_y2[(size_t)BATCH * 64 * HH * WW];
__device__ double g_sum[3][128];
__device__ double g_sumsq[3][128];
__device__ float  g_scale[1][128];                      // layer0 only
__device__ float  g_shift[1][128];
__device__ float  g_zraw[2][BATCH][128];
__device__ float  g_w1T[3 * 9 * 32];
__device__ float  g_w2T[32 * 9 * 64];
__device__ __nv_bfloat16 g_w3hi[9 * 128 * 64];          // [tap][cout][ci]
__device__ __nv_bfloat16 g_w3lo[9 * 128 * 64];
__device__ __nv_bfloat16 g_a3hi[(size_t)BATCH * HH * WW * 64];  // NHWC
__device__ __nv_bfloat16 g_a3lo[(size_t)BATCH * HH * WW * 64];

// ---------------- PTX helpers (baseline ISA only: sm_80-era) -----------------
__device__ __forceinline__ uint32_t smem_u32(const void* p) {
    uint32_t a;
    asm("{ .reg .u64 t; cvta.to.shared.u64 t, %1; cvt.u32.u64 %0, t; }" : "=r"(a) : "l"(p));
    return a;
}
__device__ __forceinline__ void ldmA(uint32_t* a, uint32_t addr) {
    asm volatile("ldmatrix.sync.aligned.m8n8.x4.shared.b16 {%0,%1,%2,%3}, [%4];"
        : "=r"(a[0]), "=r"(a[1]), "=r"(a[2]), "=r"(a[3]) : "r"(addr));
}
__device__ __forceinline__ void ldmB(uint32_t* b2, uint32_t addr) {
    asm volatile("ldmatrix.sync.aligned.m8n8.x2.shared.b16 {%0,%1}, [%2];"
        : "=r"(b2[0]), "=r"(b2[1]) : "r"(addr));
}
__device__ __forceinline__ void mma16816(float* c, const uint32_t* a, const uint32_t* b2) {
    asm volatile("mma.sync.aligned.m16n8k16.row.col.f32.bf16.bf16.f32 "
        "{%0,%1,%2,%3}, {%4,%5,%6,%7}, {%8,%9}, {%0,%1,%2,%3};"
        : "+f"(c[0]), "+f"(c[1]), "+f"(c[2]), "+f"(c[3])
        : "r"(a[0]), "r"(a[1]), "r"(a[2]), "r"(a[3]), "r"(b2[0]), "r"(b2[1]));
}

// ---------------- f32x2 helpers (conv1/conv2) --------------------------------
__device__ __forceinline__ void ffma2(unsigned long long& acc, unsigned long long a,
                                      unsigned long long w) {
    asm("fma.rn.f32x2 %0, %1, %2, %0;" : "+l"(acc) : "l"(a), "l"(w));
}
__device__ __forceinline__ unsigned long long pack2(float w) {
    unsigned long long r; asm("mov.b64 %0, {%1, %1};" : "=l"(r) : "f"(w)); return r;
}
__device__ __forceinline__ float lo2(unsigned long long u) { return __uint_as_float((unsigned)u); }
__device__ __forceinline__ float hi2(unsigned long long u) { return __uint_as_float((unsigned)(u >> 32)); }

// ---------------- prep: zero stats + transposes + w3 split -------------------
__global__ void prep_kernel(const float* __restrict__ w1, const float* __restrict__ w2,
                            const float* __restrict__ w3) {
    int idx = blockIdx.x * 256 + threadIdx.x;
    if (idx < 384) { ((double*)g_sum)[idx] = 0.0; ((double*)g_sumsq)[idx] = 0.0; }
    if (idx < 32 * 3 * 9) {
        int co = idx / 27, r = idx % 27, ci = r / 9, t = r % 9;
        g_w1T[(ci * 9 + t) * 32 + co] = w1[idx];
    }
    if (idx < 64 * 32 * 9) {
        int co = idx / 288, r = idx % 288, ci = r / 9, t = r % 9;
        g_w2T[(ci * 9 + t) * 64 + co] = w2[idx];
    }
    if (idx < 128 * 64 * 9) {
        int co = idx / 576, rem = idx % 576, ci = rem / 9, t = rem % 9;
        float w = w3[idx];
        __nv_bfloat16 hi = __float2bfloat16(w);
        __nv_bfloat16 lo = __float2bfloat16(w - __bfloat162float(hi));
        int o = (t * 128 + co) * 64 + ci;
        g_w3hi[o] = hi; g_w3lo[o] = lo;
    }
}

__global__ void bnparams_kernel(const float* __restrict__ gamma, const float* __restrict__ beta) {
    int c = threadIdx.x;
    if (c < 32) {
        const double n = (double)BATCH * HH * WW;
        double mean = g_sum[0][c] / n;
        double var  = g_sumsq[0][c] / n - mean * mean;
        float sc = gamma[c] * (float)(1.0 / sqrt(var + 1e-5));
        g_scale[0][c] = sc;
        g_shift[0][c] = beta[c] - (float)mean * sc;
    }
}

// ---------------- fused conv + stats (fp32) for conv1/conv2 ------------------
template <int CIN, int CK, int GROUPS, int LAYER_IN, int LAYER_OUT>
__global__ __launch_bounds__(128)
void conv_kernel(const float* __restrict__ in, const float* __restrict__ wT,
                 const float* __restrict__ bias, float* __restrict__ out) {
    constexpr int COUT = GROUPS * 32;
    __shared__ alignas(16) float2 s_in[CK][10][34];
    __shared__ float s_w[CK][9][32];
    __shared__ float s_out[4][32][33];
    __shared__ float s_red[2][4][32];

    const int tid = threadIdx.x, lane = tid & 31, warp = tid >> 5;
    const int b = blockIdx.z / GROUPS, g = blockIdx.z % GROUPS;
    const int gy0 = blockIdx.y * 8, gx0 = blockIdx.x * 32;
    const int cout = g * 32 + lane, row0 = 2 * warp;

    unsigned long long accA[16], accB[16];
#pragma unroll
    for (int k = 0; k < 16; ++k) { accA[k] = 0ull; accB[k] = 0ull; }

    for (int cc = 0; cc < CIN; cc += CK) {
        __syncthreads();
        for (int idx = tid; idx < CK * 10 * 33; idx += 128) {
            int ci = idx / 330, rem = idx - ci * 330;
            int r = rem / 33, c = rem - r * 33;
            int iy = gy0 - 1 + r;
            float v0 = 0.f, v1 = 0.f;
            if ((unsigned)iy < 256u) {
                int ch = cc + ci;
                const float* base = in + (((size_t)b * CIN + ch) * HH + iy) * WW;
                float sc = 1.f, sh = 0.f;
                if constexpr (LAYER_IN >= 0) { sc = g_scale[0][ch]; sh = g_shift[0][ch]; }
                int ix0 = gx0 - 1 + c;
                if ((unsigned)ix0 < 256u) {
                    v0 = base[ix0];
                    if constexpr (LAYER_IN >= 0) {
                        float t = fmaf(v0, sc, sh); v0 = (t >= 0.f) ? t : 0.01f * t;
                    }
                }
                int ix1 = ix0 + 1;
                if ((unsigned)ix1 < 256u) {
                    v1 = base[ix1];
                    if constexpr (LAYER_IN >= 0) {
                        float t = fmaf(v1, sc, sh); v1 = (t >= 0.f) ? t : 0.01f * t;
                    }
                }
            }
            s_in[ci][r][c] = make_float2(v0, v1);
        }
        for (int idx = tid; idx < CK * 9 * 32; idx += 128) {
            int ci = idx / 288, rem = idx - ci * 288;
            int t = rem >> 5, co = rem & 31;
            s_w[ci][t][co] = wT[((size_t)(cc + ci) * 9 + t) * COUT + g * 32 + co];
        }
        __syncthreads();
        for (int ci = 0; ci < CK; ++ci) {
            unsigned long long wp[9];
#pragma unroll
            for (int t = 0; t < 9; ++t) wp[t] = pack2(s_w[ci][t][lane]);
#pragma unroll
            for (int ri = 0; ri < 4; ++ri) {
                const unsigned long long* rp = (const unsigned long long*)&s_in[ci][row0 + ri][0];
                const ulonglong2* rp2 = (const ulonglong2*)rp;
                ulonglong2 q = rp2[0];
#pragma unroll
                for (int k = 0; k < 16; ++k) {
                    unsigned long long Ek = q.x, Ok = q.y, En;
                    if (k < 15) { q = rp2[k + 1]; En = q.x; } else { En = rp[32]; }
                    if (ri <= 2) {
                        ffma2(accA[k], Ek, wp[3 * ri]);
                        ffma2(accA[k], Ok, wp[3 * ri + 1]);
                        ffma2(accA[k], En, wp[3 * ri + 2]);
                    }
                    if (ri >= 1) {
                        ffma2(accB[k], Ek, wp[3 * ri - 3]);
                        ffma2(accB[k], Ok, wp[3 * ri - 2]);
                        ffma2(accB[k], En, wp[3 * ri - 1]);
                    }
                }
            }
        }
    }

    const float bv = bias[cout];
    float lsum = 0.f, lsq = 0.f;
#pragma unroll
    for (int k = 0; k < 16; ++k) {
        float a0 = lo2(accA[k]) + bv, a1 = hi2(accA[k]) + bv;
        float b0 = lo2(accB[k]) + bv, b1 = hi2(accB[k]) + bv;
        lsum += (a0 + a1) + (b0 + b1);
        lsq = fmaf(a0, a0, lsq); lsq = fmaf(a1, a1, lsq);
        lsq = fmaf(b0, b0, lsq); lsq = fmaf(b1, b1, lsq);
    }
    s_red[0][warp][lane] = lsum; s_red[1][warp][lane] = lsq;
    __syncthreads();
    if (warp == 0) {
        float ts = (s_red[0][0][lane] + s_red[0][1][lane]) + (s_red[0][2][lane] + s_red[0][3][lane]);
        float tq = (s_red[1][0][lane] + s_red[1][1][lane]) + (s_red[1][2][lane] + s_red[1][3][lane]);
        atomicAdd(&g_sum[LAYER_OUT][cout], (double)ts);
        atomicAdd(&g_sumsq[LAYER_OUT][cout], (double)tq);
    }
#pragma unroll
    for (int h = 0; h < 2; ++h) {
        __syncthreads();
        if ((warp >> 1) == h) {
            int sr = row0 - 4 * h;
#pragma unroll
            for (int k = 0; k < 16; ++k) {
                s_out[sr][2 * k][lane]     = lo2(accA[k]) + bv;
                s_out[sr][2 * k + 1][lane] = hi2(accA[k]) + bv;
                s_out[sr + 1][2 * k][lane]     = lo2(accB[k]) + bv;
                s_out[sr + 1][2 * k + 1][lane] = hi2(accB[k]) + bv;
            }
        }
        __syncthreads();
        for (int combo = warp; combo < 128; combo += 4) {
            int r = combo >> 5, co = combo & 31;
            out[(((size_t)b * COUT + g * 32 + co) * HH + gy0 + 4 * h + r) * WW + gx0 + lane] =
                s_out[r][lane][co];
        }
    }
}

// ---------------- convert: BN2(inline)+LReLU -> NHWC bf16 hi/lo --------------
__global__ __launch_bounds__(256)
void convert_kernel(const float* __restrict__ gamma, const float* __restrict__ beta) {
    __shared__ float s_sc[64], s_sh[64];
    int y = blockIdx.x, b = blockIdx.y, x = threadIdx.x;
    if (threadIdx.x < 64) {
        int c = threadIdx.x;
        const double n = (double)BATCH * HH * WW;
        double mean = g_sum[1][c] / n;
        double var  = g_sumsq[1][c] / n - mean * mean;
        float sc = gamma[c] * (float)(1.0 / sqrt(var + 1e-5));
        s_sc[c] = sc; s_sh[c] = beta[c] - (float)mean * sc;
    }
    __syncthreads();
    unsigned hi[32], lo[32];
#pragma unroll
    for (int c = 0; c < 64; c += 2) {
        float v0 = g_y2[(((size_t)b * 64 + c) * 256 + y) * 256 + x];
        float v1 = g_y2[(((size_t)b * 64 + c + 1) * 256 + y) * 256 + x];
        v0 = fmaf(v0, s_sc[c], s_sh[c]);     v0 = v0 >= 0.f ? v0 : 0.01f * v0;
        v1 = fmaf(v1, s_sc[c + 1], s_sh[c + 1]); v1 = v1 >= 0.f ? v1 : 0.01f * v1;
        __nv_bfloat16 h0 = __float2bfloat16(v0), h1 = __float2bfloat16(v1);
        __nv_bfloat16 l0 = __float2bfloat16(v0 - __bfloat162float(h0));
        __nv_bfloat16 l1 = __float2bfloat16(v1 - __bfloat162float(h1));
        hi[c / 2] = (unsigned)__bfloat16_as_ushort(h0) | ((unsigned)__bfloat16_as_ushort(h1) << 16);
        lo[c / 2] = (unsigned)__bfloat16_as_ushort(l0) | ((unsigned)__bfloat16_as_ushort(l1) << 16);
    }
    size_t p = (((size_t)b * 256 + y) * 256 + x) * 64;
#pragma unroll
    for (int c = 0; c < 8; ++c) {
        ((uint4*)(g_a3hi + p))[c] = ((uint4*)hi)[c];
        ((uint4*)(g_a3lo + p))[c] = ((uint4*)lo)[c];
    }
}

// ---------------- conv3 via warp-level mma.sync (bf16 hi/lo, 3 terms) --------
// CTA: 128 px (row y, x0..x0+127) x 128 couts. 8 warps: warp tile 64x32.
// Smem rows padded to 72 bf16 = 144B (144/4 = 36 = 4 mod 32 -> ldmatrix conflict-free).
__global__ __launch_bounds__(256)
void conv3_mma_kernel(const int* __restrict__ anchors, const int* __restrict__ positives,
                      const float* __restrict__ bias) {
    extern __shared__ char sm[];
    const uint32_t smb = smem_u32(sm);
    const int tid = threadIdx.x, lane = tid & 31, warp = tid >> 5;
    const int x0 = blockIdx.x * 128, y = blockIdx.y, b = blockIdx.z;
    const int wm = warp & 1, wn = warp >> 1;          // 2 x 4 warp grid

    const uint32_t offAh = 0, offAl = 18432, offBh = 36864, offBl = 55296;

    float acc[4][4][4];
#pragma unroll
    for (int i = 0; i < 4; ++i)
#pragma unroll
        for (int j = 0; j < 4; ++j)
#pragma unroll
            for (int c = 0; c < 4; ++c) acc[i][j][c] = 0.f;

    const int px = tid >> 1, h = tid & 1;             // staging role

    for (int t = 0; t < 9; ++t) {
        __syncthreads();
        int dy = t / 3, dx = t % 3;
        // ---- stage A (activations) hi/lo -------------------------------
        {
            int gy = y + dy - 1, gx = x0 + px + dx - 1;
            bool ok = ((unsigned)gy < 256u) && ((unsigned)gx < 256u);
            size_t src = ((((size_t)b * 256 + gy) * 256 + gx) * 64 + h * 32);
            uint32_t dst = (uint32_t)px * 144 + h * 64;
            const uint4* shp = (const uint4*)(g_a3hi + src);
            const uint4* slp = (const uint4*)(g_a3lo + src);
#pragma unroll
            for (int c = 0; c < 4; ++c) {
                uint4 vh = ok ? shp[c] : make_uint4(0, 0, 0, 0);
                uint4 vl = ok ? slp[c] : make_uint4(0, 0, 0, 0);
                *(uint4*)(sm + offAh + dst + c * 16) = vh;
                *(uint4*)(sm + offAl + dst + c * 16) = vl;
            }
        }
        // ---- stage B (weights) hi/lo -----------------------------------
        {
            size_t src = (((size_t)t * 128 + px) * 64 + h * 32);
            uint32_t dst = (uint32_t)px * 144 + h * 64;
            const uint4* shp = (const uint4*)(g_w3hi + src);
            const uint4* slp = (const uint4*)(g_w3lo + src);
#pragma unroll
            for (int c = 0; c < 4; ++c) {
                *(uint4*)(sm + offBh + dst + c * 16) = shp[c];
                *(uint4*)(sm + offBl + dst + c * 16) = slp[c];
            }
        }
        __syncthreads();
        // ---- compute: 4 k-steps x (4x4 frags) x 3 terms ---------------
#pragma unroll
        for (int kt = 0; kt < 4; ++kt) {
            uint32_t Ah[4][4], Al[4][4];
            uint32_t acol = kt * 32 + ((lane & 16) ? 16 : 0);
#pragma unroll
            for (int i = 0; i < 4; ++i) {
                uint32_t row = (uint32_t)(wm * 64 + i * 16 + (lane & 15));
                ldmA(Ah[i], smb + offAh + row * 144 + acol);
                ldmA(Al[i], smb + offAl + row * 144 + acol);
            }
            uint32_t bcol = kt * 32 + ((lane & 8) ? 16 : 0);
#pragma unroll
            for (int j = 0; j < 4; ++j) {
                uint32_t brow = (uint32_t)(wn * 32 + j * 8 + (lane & 7));
                uint32_t bh[2], bl[2];
                ldmB(bh, smb + offBh + brow * 144 + bcol);
                ldmB(bl, smb + offBl + brow * 144 + bcol);
#pragma unroll
                for (int i = 0; i < 4; ++i) {
                    mma16816(acc[i][j], Ah[i], bh);
                    mma16816(acc[i][j], Al[i], bh);
                    mma16816(acc[i][j], Ah[i], bl);
                }
            }
        }
    }

    // ---- epilogue: C + bias -> smem tile [128][132] ------------------------
    __syncthreads();
    float* tile = (float*)sm;
#pragma unroll
    for (int j = 0; j < 4; ++j) {
        int col = wn * 32 + j * 8 + (lane & 3) * 2;
        float bv0 = bias[col], bv1 = bias[col + 1];
#pragma unroll
        for (int i = 0; i < 4; ++i) {
            int r = wm * 64 + i * 16 + (lane >> 2);
            tile[r * 132 + col]           = acc[i][j][0] + bv0;
            tile[r * 132 + col + 1]       = acc[i][j][1] + bv1;
            tile[(r + 8) * 132 + col]     = acc[i][j][2] + bv0;
            tile[(r + 8) * 132 + col + 1] = acc[i][j][3] + bv1;
        }
    }
    __syncthreads();
    if (tid < 128) {
        int co = tid;
        float ss = 0.f, sq = 0.f;
        for (int p = 0; p < 128; ++p) {
            float v = tile[p * 132 + co];
            ss += v; sq = fmaf(v, v, sq);
        }
        atomicAdd(&g_sum[2][co],   (double)ss);
        atomicAdd(&g_sumsq[2][co], (double)sq);
        int ah_ = anchors[b * 8 + 6], aw_ = anchors[b * 8 + 7];
        if (ah_ == y && aw_ >= x0 && aw_ < x0 + 128)
            g_zraw[0][b][co] = tile[(aw_ - x0) * 132 + co];
        int ph_ = positives[b * 8 + 6], pw_ = positives[b * 8 + 7];
        if (ph_ == y && pw_ >= x0 && pw_ < x0 + 128)
            g_zraw[1][b][co] = tile[(pw_ - x0) * 132 + co];
    }
}

// ---------------- final: BN3(inline) + outputs + recon GEMM + patches --------
__global__ void final_kernel(const float* __restrict__ x, const int* __restrict__ anchors,
                             const int* __restrict__ positives,
                             const float* __restrict__ bn3_g, const float* __restrict__ bn3_b,
                             const float* __restrict__ recon_w, const float* __restrict__ recon_b,
                             float* __restrict__ out) {
    __shared__ float za[128], s_sc[128], s_sh[128];
    const int b = blockIdx.x, tid = threadIdx.x;
    if (tid < 128) {
        const double n = (double)BATCH * HH * WW;
        double mean = g_sum[2][tid] / n;
        double var  = g_sumsq[2][tid] / n - mean * mean;
        float sc = bn3_g[tid] * (float)(1.0 / sqrt(var + 1e-5));
        s_sc[tid] = sc; s_sh[tid] = bn3_b[tid] - (float)mean * sc;
    }
    __syncthreads();
    if (tid < 128) {
        float v = fmaf(g_zraw[0][b][tid], s_sc[tid], s_sh[tid]);
        v = (v >= 0.f) ? v : 0.01f * v;
        za[tid] = v;
        out[4704 + b * 128 + tid] = v;
        float vp = fmaf(g_zraw[1][b][tid], s_sc[tid], s_sh[tid]);
        vp = (vp >= 0.f) ? vp : 0.01f * vp;
        out[6752 + b * 128 + tid] = vp;
    }
    __syncthreads();
    if (tid < 147) {
        int ah = anchors[b * 8 + 6], aw = anchors[b * 8 + 7];
        int c = tid / 49, rem = tid % 49, i = rem / 7, j = rem % 7;
        out[b * 147 + tid] = x[(((size_t)b * 3 + c) * HH + (ah - 3 + i)) * WW + (aw - 3 + j)];
        float sum = recon_b[tid];
#pragma unroll 4
        for (int cc = 0; cc < 128; ++cc)
            sum = fmaf(za[cc], recon_w[tid * 128 + cc], sum);
        out[2352 + b * 147 + tid] = sum;
    }
}

// ---------------- launch -----------------------------------------------------
extern "C" void kernel_launch(void* const* d_in, const int* in_sizes, int n_in,
                              void* d_out, int out_size) {
    (void)in_sizes; (void)n_in; (void)out_size;
    const float* x        = (const float*)d_in[0];
    const int*   anchors  = (const int*)  d_in[1];
    const int*   positives= (const int*)  d_in[2];
    const float* conv1_w  = (const float*)d_in[3];
    const float* conv1_b  = (const float*)d_in[4];
    const float* bn1_g    = (const float*)d_in[5];
    const float* bn1_b    = (const float*)d_in[6];
    const float* conv2_w  = (const float*)d_in[7];
    const float* conv2_b  = (const float*)d_in[8];
    const float* bn2_g    = (const float*)d_in[9];
    const float* bn2_b    = (const float*)d_in[10];
    const float* conv3_w  = (const float*)d_in[11];
    const float* conv3_b  = (const float*)d_in[12];
    const float* bn3_g    = (const float*)d_in[13];
    const float* bn3_b    = (const float*)d_in[14];
    const float* recon_w  = (const float*)d_in[15];
    const float* recon_b  = (const float*)d_in[16];
    float* out = (float*)d_out;

    float *p_y1, *p_y2, *p_w1T, *p_w2T;
    cudaGetSymbolAddress((void**)&p_y1,  g_y1);
    cudaGetSymbolAddress((void**)&p_y2,  g_y2);
    cudaGetSymbolAddress((void**)&p_w1T, g_w1T);
    cudaGetSymbolAddress((void**)&p_w2T, g_w2T);

    cudaFuncSetAttribute(conv3_mma_kernel,
                         cudaFuncAttributeMaxDynamicSharedMemorySize, 73728);

    prep_kernel<<<288, 256>>>(conv1_w, conv2_w, conv3_w);                   // 1
    dim3 grid1(WW / 32, HH / 8, BATCH);
    conv_kernel<3, 3, 1, -1, 0><<<grid1, 128>>>(x, p_w1T, conv1_b, p_y1);  // 2
    bnparams_kernel<<<1, 32>>>(bn1_g, bn1_b);                              // 3
    dim3 grid2(WW / 32, HH / 8, BATCH * 2);
    conv_kernel<32, 8, 2, 0, 1><<<grid2, 128>>>(p_y1, p_w2T, conv2_b, p_y2); // 4
    convert_kernel<<<dim3(256, 16), 256>>>(bn2_g, bn2_b);                  // 5
    dim3 grid3(2, 256, BATCH);
    conv3_mma_kernel<<<grid3, 256, 73728>>>(anchors, positives, conv3_b);  // 6 (ncu target)
    final_kernel<<<BATCH, 256>>>(x, anchors, positives, bn3_g, bn3_b,
                                 recon_w, recon_b, out);                   // 7
}